// round 15
// baseline (speedup 1.0000x reference)
#include <cuda_runtime.h>
#include <cstdint>

// SqueezeLayer: checkerboard space-to-depth.
// out[b, 4c + 2*kh + kw, h2, w2] = x[b, c, 2*h2 + kh, 2*w2 + kw]
// Shapes: x (8, 64, 512, 512) f32 -> out (8, 256, 256, 256) f32.
//
// R2: 16 floats per thread (4x LDG.128 -> 4x STG.128). One warp = one full
// input row: 2KB contiguous read, two 1KB contiguous writes (kw=0 / kw=1
// channels). MLP per thread = 4 independent loads; streaming cache hints.

static constexpr int B  = 8;
static constexpr int C  = 64;
static constexpr int H  = 512;
static constexpr int W  = 512;
static constexpr int H2 = H / 2;   // 256
static constexpr int W2 = W / 2;   // 256
static constexpr int T_PER_ROW = W / 16;       // 32 threads per input row (16 floats each)
static constexpr long long TOTAL_T = (long long)B * C * H * T_PER_ROW; // 8,388,608

__global__ void squeeze_kernel(const float4* __restrict__ in4,
                               float4* __restrict__ out4) {
    unsigned tid = blockIdx.x * blockDim.x + threadIdx.x;  // < 8.4M

    // Decompose: tid = ((bc * H) + h) * T_PER_ROW + t
    unsigned t  = tid & (T_PER_ROW - 1);      // % 32
    unsigned r  = tid >> 5;                   // / 32
    unsigned h  = r & (H - 1);                // % 512
    unsigned bc = r >> 9;                     // / 512   (= b*C + c)

    unsigned kh = h & 1;
    unsigned h2 = h >> 1;

    // Four consecutive float4s: input floats [16t .. 16t+15] of row (bc, h)
    unsigned inBase = (r << 7) + (t << 2);    // r*128 + 4t (float4 units)
    float4 v0 = __ldcs(&in4[inBase + 0]);
    float4 v1 = __ldcs(&in4[inBase + 1]);
    float4 v2 = __ldcs(&in4[inBase + 2]);
    float4 v3 = __ldcs(&in4[inBase + 3]);

    // Output channel linear index: bc*4 + 2*kh  (4C == 256 so b folds in)
    unsigned outCh = (bc << 2) + (kh << 1);

    // Even elements go to out[outCh, h2, 8t .. 8t+7]  -> float4 idx base:
    unsigned base4 = (outCh * H2 + h2) * (W2 / 4) + (t << 1);
    constexpr unsigned chStride4 = H2 * W2 / 4;   // one channel in float4 units

    // kw = 0 channel: even input elements
    __stcs(&out4[base4 + 0], make_float4(v0.x, v0.z, v1.x, v1.z));
    __stcs(&out4[base4 + 1], make_float4(v2.x, v2.z, v3.x, v3.z));
    // kw = 1 channel: odd input elements
    __stcs(&out4[base4 + chStride4 + 0], make_float4(v0.y, v0.w, v1.y, v1.w));
    __stcs(&out4[base4 + chStride4 + 1], make_float4(v2.y, v2.w, v3.y, v3.w));
}

extern "C" void kernel_launch(void* const* d_in, const int* in_sizes, int n_in,
                              void* d_out, int out_size) {
    const float4* in4 = (const float4*)d_in[0];
    float4* out4 = (float4*)d_out;

    const int threads = 256;
    const long long blocks = (TOTAL_T + threads - 1) / threads;  // 32768
    squeeze_kernel<<<(unsigned)blocks, threads>>>(in4, out4);
}

// round 16
// speedup vs baseline: 1.0148x; 1.0148x over previous
#include <cuda_runtime.h>
#include <cstdint>

// SqueezeLayer: checkerboard space-to-depth.
// out[b, 4c + 2*kh + kw, h2, w2] = x[b, c, 2*h2 + kh, 2*w2 + kw]
// Shapes: x (8, 64, 512, 512) f32 -> out (8, 256, 256, 256) f32.
//
// Measured-best structure (R1): 8 floats per thread, 2x LDG.128 ->
// de-interleave -> 2x STG.128, streaming cache hints. MLP_p1=2 per thread is
// the sweet spot: deeper unrolls (4x LDG.128) raised L1tex queue pressure and
// regressed DRAM throughput. This round: 512-thread blocks to halve CTA count
// (fewer wave-transition boundaries), occupancy pinned via __launch_bounds__.

static constexpr int B  = 8;
static constexpr int C  = 64;
static constexpr int H  = 512;
static constexpr int W  = 512;
static constexpr int H2 = H / 2;   // 256
static constexpr int W2 = W / 2;   // 256
static constexpr int T_PER_ROW = W / 8;        // 64 threads per input row (8 floats each)
static constexpr long long TOTAL_T = (long long)B * C * H * T_PER_ROW; // 16,777,216

__global__ void __launch_bounds__(512)
squeeze_kernel(const float4* __restrict__ in4,
               float4* __restrict__ out4) {
    unsigned tid = blockIdx.x * blockDim.x + threadIdx.x;  // < 16.8M

    // Decompose: tid = ((bc * H) + h) * T_PER_ROW + t
    unsigned t  = tid & (T_PER_ROW - 1);      // % 64
    unsigned r  = tid >> 6;                   // / 64
    unsigned h  = r & (H - 1);                // % 512
    unsigned bc = r >> 9;                     // / 512   (= b*C + c)

    unsigned kh = h & 1;
    unsigned h2 = h >> 1;

    // Two consecutive float4s: input floats [8t .. 8t+7] of row (bc, h)
    unsigned inBase = (r << 7) + (t << 1);    // r*128 + 2t (float4 units)
    float4 v0 = __ldcs(&in4[inBase]);
    float4 v1 = __ldcs(&in4[inBase + 1]);

    // Output channel linear index: bc*4 + 2*kh  (4C == 256 so b folds in)
    unsigned outCh = (bc << 2) + (kh << 1);

    // float4 offset of out[outCh, h2, 8t/2]: ((outCh*H2 + h2)*W2)/4 + t
    unsigned base4 = (outCh * H2 + h2) * (W2 / 4) + t;
    constexpr unsigned chStride4 = H2 * W2 / 4;   // one channel in float4 units

    // kw = 0 channel: even input elements
    __stcs(&out4[base4], make_float4(v0.x, v0.z, v1.x, v1.z));
    // kw = 1 channel: odd input elements
    __stcs(&out4[base4 + chStride4], make_float4(v0.y, v0.w, v1.y, v1.w));
}

extern "C" void kernel_launch(void* const* d_in, const int* in_sizes, int n_in,
                              void* d_out, int out_size) {
    const float4* in4 = (const float4*)d_in[0];
    float4* out4 = (float4*)d_out;

    const int threads = 512;
    const long long blocks = (TOTAL_T + threads - 1) / threads;  // 32768
    squeeze_kernel<<<(unsigned)blocks, threads>>>(in4, out4);
}

// round 17
// speedup vs baseline: 1.0150x; 1.0002x over previous
#include <cuda_runtime.h>
#include <cstdint>

// SqueezeLayer: checkerboard space-to-depth.
// out[b, 4c + 2*kh + kw, h2, w2] = x[b, c, 2*h2 + kh, 2*w2 + kw]
// Shapes: x (8, 64, 512, 512) f32 -> out (8, 256, 256, 256) f32.
//
// Measured-best structure (R1): 8 floats per thread, 2x LDG.128 ->
// de-interleave -> 2x STG.128, streaming cache hints. MLP_p1=2 per thread is
// the sweet spot: deeper unrolls (4x LDG.128) raised L1tex queue pressure and
// regressed DRAM throughput. This round: 512-thread blocks to halve CTA count
// (fewer wave-transition boundaries), occupancy pinned via __launch_bounds__.

static constexpr int B  = 8;
static constexpr int C  = 64;
static constexpr int H  = 512;
static constexpr int W  = 512;
static constexpr int H2 = H / 2;   // 256
static constexpr int W2 = W / 2;   // 256
static constexpr int T_PER_ROW = W / 8;        // 64 threads per input row (8 floats each)
static constexpr long long TOTAL_T = (long long)B * C * H * T_PER_ROW; // 16,777,216

__global__ void __launch_bounds__(512)
squeeze_kernel(const float4* __restrict__ in4,
               float4* __restrict__ out4) {
    unsigned tid = blockIdx.x * blockDim.x + threadIdx.x;  // < 16.8M

    // Decompose: tid = ((bc * H) + h) * T_PER_ROW + t
    unsigned t  = tid & (T_PER_ROW - 1);      // % 64
    unsigned r  = tid >> 6;                   // / 64
    unsigned h  = r & (H - 1);                // % 512
    unsigned bc = r >> 9;                     // / 512   (= b*C + c)

    unsigned kh = h & 1;
    unsigned h2 = h >> 1;

    // Two consecutive float4s: input floats [8t .. 8t+7] of row (bc, h)
    unsigned inBase = (r << 7) + (t << 1);    // r*128 + 2t (float4 units)
    float4 v0 = __ldcs(&in4[inBase]);
    float4 v1 = __ldcs(&in4[inBase + 1]);

    // Output channel linear index: bc*4 + 2*kh  (4C == 256 so b folds in)
    unsigned outCh = (bc << 2) + (kh << 1);

    // float4 offset of out[outCh, h2, 8t/2]: ((outCh*H2 + h2)*W2)/4 + t
    unsigned base4 = (outCh * H2 + h2) * (W2 / 4) + t;
    constexpr unsigned chStride4 = H2 * W2 / 4;   // one channel in float4 units

    // kw = 0 channel: even input elements
    __stcs(&out4[base4], make_float4(v0.x, v0.z, v1.x, v1.z));
    // kw = 1 channel: odd input elements
    __stcs(&out4[base4 + chStride4], make_float4(v0.y, v0.w, v1.y, v1.w));
}

extern "C" void kernel_launch(void* const* d_in, const int* in_sizes, int n_in,
                              void* d_out, int out_size) {
    const float4* in4 = (const float4*)d_in[0];
    float4* out4 = (float4*)d_out;

    const int threads = 512;
    const long long blocks = (TOTAL_T + threads - 1) / threads;  // 32768
    squeeze_kernel<<<(unsigned)blocks, threads>>>(in4, out4);
}